// round 15
// baseline (speedup 1.0000x reference)
#include <cuda_runtime.h>
#include <cuda_bf16.h>
#include <cstdint>

#define BB  2
#define CCH 64
#define HWN 4096
#define CQ  8
#define NJQ 8              // j-split ways

// ---- scratch (no allocations allowed; __device__ globals) ----
__device__ float g_sx [BB*CCH*HWN];
__device__ float g_cx [BB*CCH*HWN];
__device__ float g_q  [BB*CQ *HWN];
__device__ float g_k  [BB*CQ *HWN];
__device__ __nv_bfloat16 g_vb[BB*CCH*HWN];     // V in bf16 (MMA B operand)
__device__ float g_Ac [BB*CCH*CCH];
__device__ float g_pn [NJQ*BB*CCH*HWN];        // partial numerators
__device__ float g_pl [NJQ*BB*HWN];            // partial denominators
__device__ float g_gramp[32*BB*CCH*CCH];       // partial Gram matrices
__device__ unsigned g_cnt[BB];                 // gram completion counters

// ---- packed fp32 pair FMA (FFMA2) ----
__device__ __forceinline__ float2 ffma2(float2 a, float2 b, float2 c) {
    union U { float2 f; unsigned long long u; };
    U ua, ub, uc, ud;
    ua.f = a; ub.f = b; uc.f = c;
    asm("fma.rn.f32x2 %0, %1, %2, %3;"
        : "=l"(ud.u) : "l"(ua.u), "l"(ub.u), "l"(uc.u));
    return ud.f;
}
__device__ __forceinline__ uint32_t smem_to_u32(const void* p) {
    uint32_t a;
    asm("{ .reg .u64 t; cvta.to.shared.u64 t, %1; cvt.u32.u64 %0, t; }"
        : "=r"(a) : "l"(p));
    return a;
}
#define CVT_BF16X2(res, lo, hi) \
    asm("cvt.rn.bf16x2.f32 %0, %1, %2;" : "=r"(res) : "f"(hi), "f"(lo))
#define CP_ASYNC16(saddr, gptr) \
    asm volatile("cp.async.cg.shared.global [%0], [%1], 16;" \
        :: "r"(saddr), "l"(gptr))
#define CP_COMMIT() asm volatile("cp.async.commit_group;")
#define CP_WAIT(n)  asm volatile("cp.async.wait_group %0;" :: "n"(n))

__device__ __forceinline__ void ldsm_x2(uint32_t& r0, uint32_t& r1, uint32_t addr) {
    asm volatile("ldmatrix.sync.aligned.m8n8.x2.shared.b16 {%0, %1}, [%2];"
        : "=r"(r0), "=r"(r1) : "r"(addr));
}
__device__ __forceinline__ void mma16816(float* d, const uint32_t* a,
                                         uint32_t b0, uint32_t b1) {
    asm volatile(
        "mma.sync.aligned.m16n8k16.row.col.f32.bf16.bf16.f32 "
        "{%0,%1,%2,%3}, {%4,%5,%6,%7}, {%8,%9}, {%0,%1,%2,%3};"
        : "+f"(d[0]), "+f"(d[1]), "+f"(d[2]), "+f"(d[3])
        : "r"(a[0]), "r"(a[1]), "r"(a[2]), "r"(a[3]), "r"(b0), "r"(b1));
}

// ============================================================
// Both 3x3 conv + BN + ReLU branches. 2 horizontal px/thread,
// tile 32w x 16h, 4 co. grid (8 tiles, 16 co-groups, 2*BB).
// ============================================================
__global__ __launch_bounds__(256) void conv3_bn_relu(
    const float* __restrict__ x,
    const float* __restrict__ sW, const float* __restrict__ sb,
    const float* __restrict__ s_g, const float* __restrict__ s_b,
    const float* __restrict__ s_m, const float* __restrict__ s_v,
    const float* __restrict__ cW, const float* __restrict__ cb,
    const float* __restrict__ c_g, const float* __restrict__ c_b,
    const float* __restrict__ c_m, const float* __restrict__ c_v)
{
    const int branch = blockIdx.z >> 1;
    const int b = blockIdx.z & 1;
    const float* W    = branch ? cW  : sW;
    const float* bias = branch ? cb  : sb;
    const float* gg   = branch ? c_g : s_g;
    const float* bbp  = branch ? c_b : s_b;
    const float* mm   = branch ? c_m : s_m;
    const float* vv   = branch ? c_v : s_v;
    float* out = branch ? g_cx : g_sx;

    const int co0 = blockIdx.y * 4;
    const int tile = blockIdx.x;              // 0..7
    const int ty0 = (tile >> 1) * 16, tx0 = (tile & 1) * 32;
    const int tid = threadIdx.x;
    const int tx = tid & 15, ty = tid >> 4;   // px cols 2tx,2tx+1; row ty

    __shared__ __align__(16) float xs[16][18][34];
    __shared__ __align__(16) float ws[16][9][4];

    float2 a01 = {0,0}, a23 = {0,0};   // px0, co 0-1 / 2-3
    float2 b01 = {0,0}, b23 = {0,0};   // px1

    for (int ci0 = 0; ci0 < 64; ci0 += 16) {
        __syncthreads();
        for (int e = tid; e < 16*612; e += 256) {
            int ci = e / 612; int rem = e - ci*612;
            int r = rem / 34; int cc = rem - r*34;
            int gy = ty0 - 1 + r, gx = tx0 - 1 + cc;
            float val = 0.f;
            if ((unsigned)gy < 64u && (unsigned)gx < 64u)
                val = x[((b*64 + ci0 + ci)*64 + gy)*64 + gx];
            xs[ci][r][cc] = val;
        }
        for (int e = tid; e < 576; e += 256) {
            int ci = e / 36; int rem = e - ci*36;
            int kk = rem >> 2; int co = rem & 3;
            ws[ci][kk][co] = W[((co0+co)*64 + (ci0+ci))*9 + kk];
        }
        __syncthreads();
        #pragma unroll
        for (int ci = 0; ci < 16; ci++) {
            float v[3][4];
            #pragma unroll
            for (int dy = 0; dy < 3; dy++) {
                float2 lo = *(float2*)&xs[ci][ty+dy][2*tx];
                float2 hi = *(float2*)&xs[ci][ty+dy][2*tx+2];
                v[dy][0] = lo.x; v[dy][1] = lo.y; v[dy][2] = hi.x; v[dy][3] = hi.y;
            }
            #pragma unroll
            for (int kk = 0; kk < 9; kk++) {
                const int dy = kk / 3, dx = kk - dy*3;
                float2 w01 = *(float2*)&ws[ci][kk][0];
                float2 w23 = *(float2*)&ws[ci][kk][2];
                float2 p0 = {v[dy][dx],   v[dy][dx]};
                float2 p1 = {v[dy][dx+1], v[dy][dx+1]};
                a01 = ffma2(p0, w01, a01);  a23 = ffma2(p0, w23, a23);
                b01 = ffma2(p1, w01, b01);  b23 = ffma2(p1, w23, b23);
            }
        }
    }
    const int oy = ty0 + ty, ox = tx0 + 2*tx;
    float pa[4] = {a01.x, a01.y, a23.x, a23.y};
    float pb[4] = {b01.x, b01.y, b23.x, b23.y};
    #pragma unroll
    for (int co = 0; co < 4; co++) {
        int c = co0 + co;
        float scale = gg[c] * rsqrtf(vv[c] + 1e-5f);
        float sh = bbp[c] + (bias[c] - mm[c]) * scale;
        float y0 = fmaxf(pa[co]*scale + sh, 0.f);
        float y1 = fmaxf(pb[co]*scale + sh, 0.f);
        float2 r = {y0, y1};
        *(float2*)&out[((b*64 + c)*64 + oy)*64 + ox] = r;
    }
}

// ============================================================
// q + k + v in ONE launch. grid (32 n-tiles, 5, BB).
// ============================================================
__global__ __launch_bounds__(256) void qkv_k(
    const float* __restrict__ x,
    const float* __restrict__ qW, const float* __restrict__ qb,
    const float* __restrict__ kW, const float* __restrict__ kb,
    const float* __restrict__ vW, const float* __restrict__ vb)
{
    __shared__ __align__(16) float ins[64][128];
    __shared__ __align__(16) float ws[64][16];

    const int b = blockIdx.z, y = blockIdx.y, n0 = blockIdx.x * 128;
    const int tid = threadIdx.x;

    for (int e = tid; e < 64*32; e += 256) {
        int ci = e >> 5, c4 = e & 31;
        *(float4*)&ins[ci][c4*4] = *(const float4*)&x[(b*64 + ci)*HWN + n0 + c4*4];
    }
    for (int e = tid; e < 64*16; e += 256) {
        int ci = e >> 4, coL = e & 15;
        float wv;
        if (y == 0) wv = (coL < 8) ? qW[coL*64 + ci] : kW[(coL-8)*64 + ci];
        else        wv = vW[((y-1)*16 + coL)*64 + ci];
        ws[ci][coL] = wv;
    }
    __syncthreads();

    const int n   = (tid & 31) * 4;
    const int coL = (tid >> 5) * 2;
    float2 a0l={0,0}, a0h={0,0}, a1l={0,0}, a1h={0,0};
    #pragma unroll 8
    for (int ci = 0; ci < 64; ci++) {
        float4 iv = *(float4*)&ins[ci][n];
        float2 wv = *(float2*)&ws[ci][coL];
        float2 il = {iv.x, iv.y}, ih = {iv.z, iv.w};
        float2 wb0 = {wv.x, wv.x}, wb1 = {wv.y, wv.y};
        a0l = ffma2(wb0, il, a0l);  a0h = ffma2(wb0, ih, a0h);
        a1l = ffma2(wb1, il, a1l);  a1h = ffma2(wb1, ih, a1h);
    }
    #pragma unroll
    for (int rr = 0; rr < 2; rr++) {
        int c = coL + rr;
        float r0 = (rr ? a1l.x : a0l.x), r1 = (rr ? a1l.y : a0l.y);
        float r2 = (rr ? a1h.x : a0h.x), r3 = (rr ? a1h.y : a0h.y);
        if (y == 0) {
            float bv; float* o;
            if (c < 8) { bv = qb[c];   o = g_q + (size_t)(b*CQ + c  )*HWN + n0 + n; }
            else       { bv = kb[c-8]; o = g_k + (size_t)(b*CQ + c-8)*HWN + n0 + n; }
            float4 rv = {r0+bv, r1+bv, r2+bv, r3+bv};
            *(float4*)o = rv;
        } else {
            int cv = (y-1)*16 + c;
            float bv = vb[cv];
            __nv_bfloat16* o = g_vb + (size_t)(b*CCH + cv)*HWN + n0 + n;
            uint32_t p0, p1;
            CVT_BF16X2(p0, r0+bv, r1+bv);
            CVT_BF16X2(p1, r2+bv, r3+bv);
            *(uint2*)o = make_uint2(p0, p1);
        }
    }
}

// ============================================================
// MID: attn (512 CTAs) + gram partials w/ last-CTA softmax (64 CTAs).
// ============================================================
#define VSTRIDE 176
#define VBUF    11264        // 64*176
#define SM_V    0            // 2 buffers: 22528
#define SM_K    22528        // 2 x 2048
#define SM_Q    26624        // 4096
#define DSTRIDE 132
#define MID_SMEM 35072       // >= max(33792 attn, 34816 gram t2)

__global__ __launch_bounds__(256) void mid_k()
{
    __shared__ __align__(16) char sm[MID_SMEM];
    const int bid = blockIdx.x;
    const int tid = threadIdx.x;

    if (bid < 512) {
        // ---------------- spatial attention ----------------
        const int i0 = (bid & 31) * 128;
        const int jq = (bid >> 5) & 7;
        const int b  = bid >> 8;
        const int wid = tid >> 5, lane = tid & 31;
        const int q = lane & 3, rr = lane >> 2;
        const uint32_t smb = smem_to_u32(sm);
        const int jbase = jq * (HWN / NJQ);

        float* Qs = (float*)(sm + SM_Q);
        {
            int e = tid * 4;
            int d = e >> 7, ii = e & 127;
            *(float4*)&Qs[e] = *(const float4*)&g_q[(size_t)(b*CQ + d)*HWN + i0 + ii];
        }

        auto stage = [&](int t, int s) {
            const int j0 = jbase + t*64;
            const uint32_t vdst = smb + SM_V + s*VBUF;
            #pragma unroll
            for (int rep = 0; rep < 2; rep++) {
                int e = tid + rep*256;
                int c = e >> 3, xo = (e & 7) * 16;
                CP_ASYNC16(vdst + c*VSTRIDE + xo,
                    (const char*)(g_vb + (size_t)(b*CCH + c)*HWN + j0) + xo);
            }
            if (tid < 128) {
                int d = tid >> 4, jj = (tid & 15) * 4;
                CP_ASYNC16(smb + SM_K + s*2048 + (d*64 + jj)*4,
                    &g_k[(size_t)(b*CQ + d)*HWN + j0 + jj]);
            }
        };

        stage(0, 0); CP_COMMIT();
        __syncthreads();   // Q visible
        float qr0[8], qr1[8];
        #pragma unroll
        for (int d = 0; d < 8; d++) {
            qr0[d] = Qs[d*128 + wid*16 + rr];
            qr1[d] = Qs[d*128 + wid*16 + rr + 8];
        }

        float acc[8][4];
        #pragma unroll
        for (int nb = 0; nb < 8; nb++)
            #pragma unroll
            for (int r = 0; r < 4; r++) acc[nb][r] = 0.f;
        float lden0 = 0.f, lden1 = 0.f;

        const int NT = HWN / NJQ / 64;    // 8 tiles
        for (int t = 0; t < NT; t++) {
            const int s = t & 1;
            if (t + 1 < NT) { stage(t + 1, s ^ 1); CP_COMMIT(); CP_WAIT(1); }
            else            { CP_WAIT(0); }
            __syncthreads();

            const float* Ks = (const float*)(sm + SM_K + s*2048);
            const uint32_t baseB = smb + SM_V + s*VBUF
                                 + (lane & 7)*VSTRIDE + ((lane >> 3) & 1)*16;

            uint32_t afr[4][4];
            #pragma unroll
            for (int kk = 0; kk < 4; kk++) {
                const int jb = kk*16 + 2*q;
                float2 s00 = {0,0}, s01 = {0,0}, s10 = {0,0}, s11 = {0,0};
                #pragma unroll
                for (int d = 0; d < 8; d++) {
                    float2 k0 = *(float2*)&Ks[d*64 + jb];
                    float2 k8 = *(float2*)&Ks[d*64 + jb + 8];
                    float2 q0 = {qr0[d], qr0[d]}, q1 = {qr1[d], qr1[d]};
                    s00 = ffma2(q0, k0, s00);  s01 = ffma2(q0, k8, s01);
                    s10 = ffma2(q1, k0, s10);  s11 = ffma2(q1, k8, s11);
                }
                float e00 = __expf(s00.x), e01 = __expf(s00.y);
                float e08 = __expf(s01.x), e09 = __expf(s01.y);
                float e10 = __expf(s10.x), e11 = __expf(s10.y);
                float e18 = __expf(s11.x), e19 = __expf(s11.y);
                lden0 += (e00 + e01) + (e08 + e09);
                lden1 += (e10 + e11) + (e18 + e19);
                CVT_BF16X2(afr[kk][0], e00, e01);
                CVT_BF16X2(afr[kk][1], e10, e11);
                CVT_BF16X2(afr[kk][2], e08, e09);
                CVT_BF16X2(afr[kk][3], e18, e19);
            }
            #pragma unroll
            for (int nb = 0; nb < 8; nb++) {
                const uint32_t anb = baseB + nb*(8*VSTRIDE);
                #pragma unroll
                for (int kk = 0; kk < 4; kk++) {
                    uint32_t b0, b1;
                    ldsm_x2(b0, b1, anb + kk*32);
                    mma16816(acc[nb], afr[kk], b0, b1);
                }
            }
            __syncthreads();
        }

        lden0 += __shfl_xor_sync(0xffffffffu, lden0, 1);
        lden0 += __shfl_xor_sync(0xffffffffu, lden0, 2);
        lden1 += __shfl_xor_sync(0xffffffffu, lden1, 1);
        lden1 += __shfl_xor_sync(0xffffffffu, lden1, 2);
        if (q == 0) {
            g_pl[(jq*BB + b)*HWN + i0 + wid*16 + rr]     = lden0;
            g_pl[(jq*BB + b)*HWN + i0 + wid*16 + rr + 8] = lden1;
        }

        float* Db = (float*)sm;
        {
            const int iL = wid*16 + rr;
            #pragma unroll
            for (int nb = 0; nb < 8; nb++) {
                const int c0 = nb*8 + 2*q;
                Db[ c0   *DSTRIDE + iL    ] = acc[nb][0];
                Db[(c0+1)*DSTRIDE + iL    ] = acc[nb][1];
                Db[ c0   *DSTRIDE + iL + 8] = acc[nb][2];
                Db[(c0+1)*DSTRIDE + iL + 8] = acc[nb][3];
            }
        }
        __syncthreads();
        float* pn = g_pn + (size_t)((jq*BB + b)*CCH)*HWN;
        for (int e = tid; e < 2048; e += 256) {
            int c = e >> 5, xx = (e & 31) * 4;
            *(float4*)&pn[(size_t)c*HWN + i0 + xx] = *(float4*)&Db[c*DSTRIDE + xx];
        }
    } else {
        // ---------------- gram partial + last-CTA softmax ----------------
        const int g = bid - 512;          // 0..63
        const int chunk = g >> 1;
        const int b = g & 1;
        const int n0 = chunk * 128;
        float (*t2)[68] = (float(*)[68])sm;
        const float* f = g_cx + (size_t)b*CCH*HWN;
        {
            int r = tid >> 2, nb = tid & 3;
            #pragma unroll
            for (int u = 0; u < 8; u++) {
                int n = nb*32 + u*4;
                float4 v = *(const float4*)&f[(size_t)r*HWN + n0 + n];
                t2[n  ][r] = v.x;
                t2[n+1][r] = v.y;
                t2[n+2][r] = v.z;
                t2[n+3][r] = v.w;
            }
        }
        __syncthreads();
        const int i4 = (tid & 15) * 4, j4 = (tid >> 4) * 4;
        float2 acc[4][2];
        #pragma unroll
        for (int a = 0; a < 4; a++) { acc[a][0] = {0,0}; acc[a][1] = {0,0}; }
        for (int n = 0; n < 128; n++) {
            float4 fi = *(float4*)&t2[n][i4];
            float4 fj = *(float4*)&t2[n][j4];
            float2 j01 = {fj.x, fj.y}, j23 = {fj.z, fj.w};
            float fa[4] = {fi.x, fi.y, fi.z, fi.w};
            #pragma unroll
            for (int a = 0; a < 4; a++) {
                float2 fb = {fa[a], fa[a]};
                acc[a][0] = ffma2(fb, j01, acc[a][0]);
                acc[a][1] = ffma2(fb, j23, acc[a][1]);
            }
        }
        float* gp = g_gramp + (size_t)(chunk*BB + b)*4096;
        #pragma unroll
        for (int a = 0; a < 4; a++) {
            float4 r = {acc[a][0].x, acc[a][0].y, acc[a][1].x, acc[a][1].y};
            *(float4*)&gp[(i4 + a)*64 + j4] = r;
        }
        // completion counter (threadFenceReduction pattern)
        __shared__ unsigned last_flag;
        __syncthreads();
        if (tid == 0) {
            __threadfence();
            unsigned old = atomicAdd(&g_cnt[b], 1u);
            last_flag = (old == 31u);
        }
        __syncthreads();
        if (last_flag) {
            __threadfence();
            float (*red)[65] = (float(*)[65])sm;
            __syncthreads();
            for (int e = tid; e < 4096; e += 256) {
                float s = 0.f;
                #pragma unroll
                for (int ch = 0; ch < 32; ch++)
                    s += g_gramp[(size_t)(ch*BB + b)*4096 + e];
                red[e >> 6][e & 63] = s;
            }
            __syncthreads();
            if (tid < 64) {
                float mn = red[tid][0];
                #pragma unroll 8
                for (int j = 1; j < 64; j++) mn = fminf(mn, red[tid][j]);
                float sum = 0.f;
                #pragma unroll 8
                for (int j = 0; j < 64; j++) {
                    float e = __expf(mn - red[tid][j]);
                    red[tid][j] = e;
                    sum += e;
                }
                float inv = 1.f / sum;
                #pragma unroll 8
                for (int j = 0; j < 64; j++)
                    g_Ac[(b*CCH + tid)*CCH + j] = red[tid][j] * inv;
            }
            if (tid == 0) g_cnt[b] = 0u;   // reset for next graph replay
        }
    }
}

// ============================================================
// EPILOGUE: sum = sg*(Σ pn)/(Σ pl) + sx + cg*(Ac@fmap) + cx   (in smem)
// then out = oW @ sum + ob  → writes d_out directly.
// grid (128 n-tiles of 32, BB), block 512 (thread owns 4 channels).
// ============================================================
__global__ __launch_bounds__(512) void ca_fuse_o_k(
    const float* __restrict__ s_gamma, const float* __restrict__ c_gamma,
    const float* __restrict__ oW, const float* __restrict__ ob,
    float* __restrict__ dout)
{
    __shared__ __align__(16) float ft[64][36];
    __shared__ __align__(16) float As[64][68];   // Ac^T, later reused for oW
    __shared__ float linv[32];
    const int b = blockIdx.y, n0 = blockIdx.x * 32, tid = threadIdx.x;
    const float* f = g_cx + (size_t)b*CCH*HWN;
    for (int e = tid; e < 512; e += 512) {
        int r = e >> 3, c4 = e & 7;
        *(float4*)&ft[r][c4*4] = *(const float4*)&f[(size_t)r*HWN + n0 + c4*4];
    }
    for (int e = tid; e < 1024; e += 512) {
        int c = e >> 4, j4 = (e & 15) * 4;
        float4 a4 = *(const float4*)&g_Ac[(b*CCH + c)*CCH + j4];
        As[j4  ][c] = a4.x;
        As[j4+1][c] = a4.y;
        As[j4+2][c] = a4.z;
        As[j4+3][c] = a4.w;
    }
    if (tid < 32) {
        float l = 0.f;
        #pragma unroll
        for (int qq = 0; qq < NJQ; qq++)
            l += g_pl[(qq*BB + b)*HWN + n0 + tid];
        linv[tid] = s_gamma[0] / l;
    }
    __syncthreads();
    const int n = tid & 31, c0 = (tid >> 5) * 4;   // 16 groups x 4 channels
    float2 acc2[2];
    acc2[0] = make_float2(0.f, 0.f);
    acc2[1] = make_float2(0.f, 0.f);
    for (int jj = 0; jj < 64; jj++) {
        float fv = ft[jj][n];
        float2 fb = {fv, fv};
        acc2[0] = ffma2(fb, *(float2*)&As[jj][c0],     acc2[0]);
        acc2[1] = ffma2(fb, *(float2*)&As[jj][c0 + 2], acc2[1]);
    }
    const float cg = c_gamma[0];
    const float li = linv[n];
    float sums[4];
    #pragma unroll
    for (int p = 0; p < 2; p++) {
        #pragma unroll
        for (int h = 0; h < 2; h++) {
            int c = c0 + p*2 + h;
            size_t idx = (size_t)(b*CCH + c)*HWN + n0 + n;
            float pnsum = 0.f;
            #pragma unroll
            for (int qq = 0; qq < NJQ; qq++)
                pnsum += g_pn[(size_t)((qq*BB + b)*CCH + c)*HWN + n0 + n];
            float ca = h ? acc2[p].y : acc2[p].x;
            sums[p*2 + h] = li*pnsum + g_sx[idx] + cg*ca + ft[c][n];
        }
    }
    __syncthreads();
    #pragma unroll
    for (int u = 0; u < 4; u++) ft[c0 + u][n] = sums[u];
    for (int e = tid; e < 4096; e += 512) {
        int ci = e >> 6, co = e & 63;
        As[ci][co] = oW[co*64 + ci];
    }
    __syncthreads();
    float2 oacc[2];
    oacc[0] = make_float2(0.f, 0.f);
    oacc[1] = make_float2(0.f, 0.f);
    for (int ci = 0; ci < 64; ci++) {
        float sv = ft[ci][n];
        float2 sb2 = {sv, sv};
        oacc[0] = ffma2(sb2, *(float2*)&As[ci][c0],     oacc[0]);
        oacc[1] = ffma2(sb2, *(float2*)&As[ci][c0 + 2], oacc[1]);
    }
    #pragma unroll
    for (int p = 0; p < 2; p++) {
        #pragma unroll
        for (int h = 0; h < 2; h++) {
            int co = c0 + p*2 + h;
            float v = (h ? oacc[p].y : oacc[p].x) + ob[co];
            dout[(size_t)(b*CCH + co)*HWN + n0 + n] = v;
        }
    }
}

// ============================================================
extern "C" void kernel_launch(void* const* d_in, const int* in_sizes, int n_in,
                              void* d_out, int out_size)
{
    const float* x   = (const float*)d_in[0];
    const float* sW  = (const float*)d_in[1];
    const float* sb  = (const float*)d_in[2];
    const float* s_g = (const float*)d_in[3];
    const float* s_b = (const float*)d_in[4];
    const float* s_m = (const float*)d_in[5];
    const float* s_v = (const float*)d_in[6];
    const float* cW  = (const float*)d_in[7];
    const float* cb  = (const float*)d_in[8];
    const float* c_g = (const float*)d_in[9];
    const float* c_b = (const float*)d_in[10];
    const float* c_m = (const float*)d_in[11];
    const float* c_v = (const float*)d_in[12];
    const float* qW  = (const float*)d_in[13];
    const float* qb  = (const float*)d_in[14];
    const float* kW  = (const float*)d_in[15];
    const float* kb  = (const float*)d_in[16];
    const float* vW  = (const float*)d_in[17];
    const float* vb  = (const float*)d_in[18];
    const float* oW  = (const float*)d_in[19];
    const float* ob  = (const float*)d_in[20];
    const float* s_gamma = (const float*)d_in[21];
    const float* c_gamma = (const float*)d_in[22];
    float* out = (float*)d_out;

    conv3_bn_relu<<<dim3(8,16,2*BB), 256>>>(x, sW, sb, s_g, s_b, s_m, s_v,
                                            cW, cb, c_g, c_b, c_m, c_v);
    qkv_k<<<dim3(32,5,BB), 256>>>(x, qW, qb, kW, kb, vW, vb);

    mid_k<<<576, 256>>>();

    ca_fuse_o_k<<<dim3(128,BB), 512>>>(s_gamma, c_gamma, oW, ob, out);
}

// round 16
// speedup vs baseline: 1.0995x; 1.0995x over previous
#include <cuda_runtime.h>
#include <cuda_bf16.h>
#include <cstdint>

#define BB  2
#define CCH 64
#define HWN 4096
#define CQ  8
#define NJQ 8              // j-split ways

// ---- scratch (no allocations allowed; __device__ globals) ----
__device__ float g_sx [BB*CCH*HWN];
__device__ float g_cx [BB*CCH*HWN];
__device__ __nv_bfloat16 g_qb[BB*HWN*CQ];      // Q bf16, [b][n][d]
__device__ __nv_bfloat16 g_kb[BB*HWN*CQ];      // K bf16, [b][n][d]
__device__ __nv_bfloat16 g_vb[BB*CCH*HWN];     // V bf16 (PV B operand)
__device__ float g_Ac [BB*CCH*CCH];
__device__ float g_pn [NJQ*BB*CCH*HWN];        // partial numerators
__device__ float g_pl [NJQ*BB*HWN];            // partial denominators
__device__ float g_gramp[32*BB*CCH*CCH];       // partial Gram matrices
__device__ unsigned g_cnt[BB];                 // gram completion counters

// ---- packed fp32 pair FMA (FFMA2) ----
__device__ __forceinline__ float2 ffma2(float2 a, float2 b, float2 c) {
    union U { float2 f; unsigned long long u; };
    U ua, ub, uc, ud;
    ua.f = a; ub.f = b; uc.f = c;
    asm("fma.rn.f32x2 %0, %1, %2, %3;"
        : "=l"(ud.u) : "l"(ua.u), "l"(ub.u), "l"(uc.u));
    return ud.f;
}
__device__ __forceinline__ uint32_t smem_to_u32(const void* p) {
    uint32_t a;
    asm("{ .reg .u64 t; cvta.to.shared.u64 t, %1; cvt.u32.u64 %0, t; }"
        : "=r"(a) : "l"(p));
    return a;
}
#define CVT_BF16X2(res, lo, hi) \
    asm("cvt.rn.bf16x2.f32 %0, %1, %2;" : "=r"(res) : "f"(hi), "f"(lo))
#define CP_ASYNC16(saddr, gptr) \
    asm volatile("cp.async.cg.shared.global [%0], [%1], 16;" \
        :: "r"(saddr), "l"(gptr))
#define CP_COMMIT() asm volatile("cp.async.commit_group;")
#define CP_WAIT(n)  asm volatile("cp.async.wait_group %0;" :: "n"(n))

__device__ __forceinline__ void ldsm_x2(uint32_t& r0, uint32_t& r1, uint32_t addr) {
    asm volatile("ldmatrix.sync.aligned.m8n8.x2.shared.b16 {%0, %1}, [%2];"
        : "=r"(r0), "=r"(r1) : "r"(addr));
}
__device__ __forceinline__ void ldsm_x4(uint32_t& r0, uint32_t& r1,
                                        uint32_t& r2, uint32_t& r3, uint32_t addr) {
    asm volatile("ldmatrix.sync.aligned.m8n8.x4.shared.b16 {%0, %1, %2, %3}, [%4];"
        : "=r"(r0), "=r"(r1), "=r"(r2), "=r"(r3) : "r"(addr));
}
__device__ __forceinline__ void mma16816(float* d, const uint32_t* a,
                                         uint32_t b0, uint32_t b1) {
    asm volatile(
        "mma.sync.aligned.m16n8k16.row.col.f32.bf16.bf16.f32 "
        "{%0,%1,%2,%3}, {%4,%5,%6,%7}, {%8,%9}, {%0,%1,%2,%3};"
        : "+f"(d[0]), "+f"(d[1]), "+f"(d[2]), "+f"(d[3])
        : "r"(a[0]), "r"(a[1]), "r"(a[2]), "r"(a[3]), "r"(b0), "r"(b1));
}
__device__ __forceinline__ void mma1688(float* d, uint32_t a0, uint32_t a1,
                                        uint32_t b0) {
    asm volatile(
        "mma.sync.aligned.m16n8k8.row.col.f32.bf16.bf16.f32 "
        "{%0,%1,%2,%3}, {%4,%5}, {%6}, {%0,%1,%2,%3};"
        : "+f"(d[0]), "+f"(d[1]), "+f"(d[2]), "+f"(d[3])
        : "r"(a0), "r"(a1), "r"(b0));
}

// ============================================================
// Both 3x3 conv + BN + ReLU branches. 2 horizontal px/thread,
// tile 32w x 16h, 4 co. grid (8 tiles, 16 co-groups, 2*BB).
// ============================================================
__global__ __launch_bounds__(256) void conv3_bn_relu(
    const float* __restrict__ x,
    const float* __restrict__ sW, const float* __restrict__ sb,
    const float* __restrict__ s_g, const float* __restrict__ s_b,
    const float* __restrict__ s_m, const float* __restrict__ s_v,
    const float* __restrict__ cW, const float* __restrict__ cb,
    const float* __restrict__ c_g, const float* __restrict__ c_b,
    const float* __restrict__ c_m, const float* __restrict__ c_v)
{
    const int branch = blockIdx.z >> 1;
    const int b = blockIdx.z & 1;
    const float* W    = branch ? cW  : sW;
    const float* bias = branch ? cb  : sb;
    const float* gg   = branch ? c_g : s_g;
    const float* bbp  = branch ? c_b : s_b;
    const float* mm   = branch ? c_m : s_m;
    const float* vv   = branch ? c_v : s_v;
    float* out = branch ? g_cx : g_sx;

    const int co0 = blockIdx.y * 4;
    const int tile = blockIdx.x;              // 0..7
    const int ty0 = (tile >> 1) * 16, tx0 = (tile & 1) * 32;
    const int tid = threadIdx.x;
    const int tx = tid & 15, ty = tid >> 4;   // px cols 2tx,2tx+1; row ty

    __shared__ __align__(16) float xs[16][18][34];
    __shared__ __align__(16) float ws[16][9][4];

    float2 a01 = {0,0}, a23 = {0,0};   // px0, co 0-1 / 2-3
    float2 b01 = {0,0}, b23 = {0,0};   // px1

    for (int ci0 = 0; ci0 < 64; ci0 += 16) {
        __syncthreads();
        for (int e = tid; e < 16*612; e += 256) {
            int ci = e / 612; int rem = e - ci*612;
            int r = rem / 34; int cc = rem - r*34;
            int gy = ty0 - 1 + r, gx = tx0 - 1 + cc;
            float val = 0.f;
            if ((unsigned)gy < 64u && (unsigned)gx < 64u)
                val = x[((b*64 + ci0 + ci)*64 + gy)*64 + gx];
            xs[ci][r][cc] = val;
        }
        for (int e = tid; e < 576; e += 256) {
            int ci = e / 36; int rem = e - ci*36;
            int kk = rem >> 2; int co = rem & 3;
            ws[ci][kk][co] = W[((co0+co)*64 + (ci0+ci))*9 + kk];
        }
        __syncthreads();
        #pragma unroll
        for (int ci = 0; ci < 16; ci++) {
            float v[3][4];
            #pragma unroll
            for (int dy = 0; dy < 3; dy++) {
                float2 lo = *(float2*)&xs[ci][ty+dy][2*tx];
                float2 hi = *(float2*)&xs[ci][ty+dy][2*tx+2];
                v[dy][0] = lo.x; v[dy][1] = lo.y; v[dy][2] = hi.x; v[dy][3] = hi.y;
            }
            #pragma unroll
            for (int kk = 0; kk < 9; kk++) {
                const int dy = kk / 3, dx = kk - dy*3;
                float2 w01 = *(float2*)&ws[ci][kk][0];
                float2 w23 = *(float2*)&ws[ci][kk][2];
                float2 p0 = {v[dy][dx],   v[dy][dx]};
                float2 p1 = {v[dy][dx+1], v[dy][dx+1]};
                a01 = ffma2(p0, w01, a01);  a23 = ffma2(p0, w23, a23);
                b01 = ffma2(p1, w01, b01);  b23 = ffma2(p1, w23, b23);
            }
        }
    }
    const int oy = ty0 + ty, ox = tx0 + 2*tx;
    float pa[4] = {a01.x, a01.y, a23.x, a23.y};
    float pb[4] = {b01.x, b01.y, b23.x, b23.y};
    #pragma unroll
    for (int co = 0; co < 4; co++) {
        int c = co0 + co;
        float scale = gg[c] * rsqrtf(vv[c] + 1e-5f);
        float sh = bbp[c] + (bias[c] - mm[c]) * scale;
        float y0 = fmaxf(pa[co]*scale + sh, 0.f);
        float y1 = fmaxf(pb[co]*scale + sh, 0.f);
        float2 r = {y0, y1};
        *(float2*)&out[((b*64 + c)*64 + oy)*64 + ox] = r;
    }
}

// ============================================================
// q + k + v in ONE launch. grid (32 n-tiles, 5, BB).
// y==0: q(d 0-7)+k(d 8-15) as bf16 [n][8]; y 1..4: v bf16 [c][n].
// ============================================================
__global__ __launch_bounds__(256) void qkv_k(
    const float* __restrict__ x,
    const float* __restrict__ qW, const float* __restrict__ qb,
    const float* __restrict__ kW, const float* __restrict__ kb,
    const float* __restrict__ vW, const float* __restrict__ vb)
{
    __shared__ __align__(16) float ins[64][128];
    __shared__ __align__(16) float ws[64][16];

    const int b = blockIdx.z, y = blockIdx.y, n0 = blockIdx.x * 128;
    const int tid = threadIdx.x;

    for (int e = tid; e < 64*32; e += 256) {
        int ci = e >> 5, c4 = e & 31;
        *(float4*)&ins[ci][c4*4] = *(const float4*)&x[(b*64 + ci)*HWN + n0 + c4*4];
    }
    for (int e = tid; e < 64*16; e += 256) {
        int ci = e >> 4, coL = e & 15;
        float wv;
        if (y == 0) wv = (coL < 8) ? qW[coL*64 + ci] : kW[(coL-8)*64 + ci];
        else        wv = vW[((y-1)*16 + coL)*64 + ci];
        ws[ci][coL] = wv;
    }
    __syncthreads();

    const int n   = (tid & 31) * 4;
    const int coL = (tid >> 5) * 2;
    float2 a0l={0,0}, a0h={0,0}, a1l={0,0}, a1h={0,0};
    #pragma unroll 8
    for (int ci = 0; ci < 64; ci++) {
        float4 iv = *(float4*)&ins[ci][n];
        float2 wv = *(float2*)&ws[ci][coL];
        float2 il = {iv.x, iv.y}, ih = {iv.z, iv.w};
        float2 wb0 = {wv.x, wv.x}, wb1 = {wv.y, wv.y};
        a0l = ffma2(wb0, il, a0l);  a0h = ffma2(wb0, ih, a0h);
        a1l = ffma2(wb1, il, a1l);  a1h = ffma2(wb1, ih, a1h);
    }
    if (y == 0) {
        const int isK = (coL >= 8);
        const int d = coL & 7;
        __nv_bfloat16* dst = isK ? g_kb : g_qb;
        float bv0 = isK ? kb[d]   : qb[d];
        float bv1 = isK ? kb[d+1] : qb[d+1];
        float v0[4] = {a0l.x+bv0, a0l.y+bv0, a0h.x+bv0, a0h.y+bv0};
        float v1[4] = {a1l.x+bv1, a1l.y+bv1, a1h.x+bv1, a1h.y+bv1};
        #pragma unroll
        for (int i = 0; i < 4; i++) {
            uint32_t pk;
            CVT_BF16X2(pk, v0[i], v1[i]);
            *(uint32_t*)(dst + ((size_t)b*HWN + n0 + n + i)*CQ + d) = pk;
        }
    } else {
        #pragma unroll
        for (int rr = 0; rr < 2; rr++) {
            int cv = (y-1)*16 + coL + rr;
            float bv = vb[cv];
            float r0 = (rr ? a1l.x : a0l.x) + bv, r1 = (rr ? a1l.y : a0l.y) + bv;
            float r2 = (rr ? a1h.x : a0h.x) + bv, r3 = (rr ? a1h.y : a0h.y) + bv;
            __nv_bfloat16* o = g_vb + (size_t)(b*CCH + cv)*HWN + n0 + n;
            uint32_t p0, p1;
            CVT_BF16X2(p0, r0, r1);
            CVT_BF16X2(p1, r2, r3);
            *(uint2*)o = make_uint2(p0, p1);
        }
    }
}

// ============================================================
// MID: attn (512 CTAs, S and PV both on HMMA)
//    + gram partials w/ last-CTA softmax (64 CTAs).
// ============================================================
#define VSTRIDE 176
#define VBUF    11264        // 64*176
#define SM_V    0            // 2 buffers: 22528
#define SM_K    22528        // 2 x 1024 (bf16)
#define SM_Q    24576        // 2048 (bf16 [128i][8d])
#define DSTRIDE 132
#define MID_SMEM 35072       // >= max(attn, 34816 gram t2, 33792 drain)

__global__ __launch_bounds__(256) void mid_k()
{
    __shared__ __align__(16) char sm[MID_SMEM];
    const int bid = blockIdx.x;
    const int tid = threadIdx.x;

    if (bid < 512) {
        // ---------------- spatial attention ----------------
        const int i0 = (bid & 31) * 128;
        const int jq = (bid >> 5) & 7;
        const int b  = bid >> 8;
        const int wid = tid >> 5, lane = tid & 31;
        const int q = lane & 3, rr = lane >> 2;
        const uint32_t smb = smem_to_u32(sm);
        const int jbase = jq * (HWN / NJQ);

        auto stage = [&](int t, int s) {
            const int j0 = jbase + t*64;
            const uint32_t vdst = smb + SM_V + s*VBUF;
            #pragma unroll
            for (int rep = 0; rep < 2; rep++) {
                int e = tid + rep*256;
                int c = e >> 3, xo = (e & 7) * 16;
                CP_ASYNC16(vdst + c*VSTRIDE + xo,
                    (const char*)(g_vb + (size_t)(b*CCH + c)*HWN + j0) + xo);
            }
            if (tid < 64) {
                CP_ASYNC16(smb + SM_K + s*1024 + tid*16,
                    (const char*)(g_kb + ((size_t)b*HWN + j0 + tid)*CQ));
            }
        };

        // Q tile (bf16 [128i][8d] = 2 KB) joins cp.async group 0
        if (tid < 128)
            CP_ASYNC16(smb + SM_Q + tid*16,
                (const char*)(g_qb + ((size_t)b*HWN + i0 + tid)*CQ));
        stage(0, 0); CP_COMMIT();

        uint32_t qa0 = 0, qa1 = 0;   // Q A-fragment (m16n8k8), loaded at t==0
        float acc[8][4];
        #pragma unroll
        for (int nb = 0; nb < 8; nb++)
            #pragma unroll
            for (int r = 0; r < 4; r++) acc[nb][r] = 0.f;
        float lden0 = 0.f, lden1 = 0.f;

        const int NT = HWN / NJQ / 64;    // 8 tiles
        for (int t = 0; t < NT; t++) {
            const int s = t & 1;
            if (t + 1 < NT) { stage(t + 1, s ^ 1); CP_COMMIT(); CP_WAIT(1); }
            else            { CP_WAIT(0); }
            __syncthreads();

            if (t == 0) {
                uint32_t qaddr = smb + SM_Q + (wid*16 + (lane & 15))*16;
                ldsm_x2(qa0, qa1, qaddr);
            }
            // ---- S = Q K^T on HMMA: 2 ldsm.x4 (B frags) + 8 mma.k8 ----
            uint32_t kfr[8];
            const uint32_t kaddr = smb + SM_K + s*1024 + lane*16;
            ldsm_x4(kfr[0], kfr[1], kfr[2], kfr[3], kaddr);        // j 0..31
            ldsm_x4(kfr[4], kfr[5], kfr[6], kfr[7], kaddr + 512);  // j 32..63
            float Ds[8][4];
            #pragma unroll
            for (int nb = 0; nb < 8; nb++) {
                Ds[nb][0] = Ds[nb][1] = Ds[nb][2] = Ds[nb][3] = 0.f;
                mma1688(Ds[nb], qa0, qa1, kfr[nb]);
            }
            // ---- exp -> bf16 A fragments ----
            uint32_t afr[4][4];
            #pragma unroll
            for (int kk = 0; kk < 4; kk++) {
                float e00 = __expf(Ds[2*kk  ][0]), e01 = __expf(Ds[2*kk  ][1]);
                float e10 = __expf(Ds[2*kk  ][2]), e11 = __expf(Ds[2*kk  ][3]);
                float e08 = __expf(Ds[2*kk+1][0]), e09 = __expf(Ds[2*kk+1][1]);
                float e18 = __expf(Ds[2*kk+1][2]), e19 = __expf(Ds[2*kk+1][3]);
                lden0 += (e00 + e01) + (e08 + e09);
                lden1 += (e10 + e11) + (e18 + e19);
                CVT_BF16X2(afr[kk][0], e00, e01);
                CVT_BF16X2(afr[kk][1], e10, e11);
                CVT_BF16X2(afr[kk][2], e08, e09);
                CVT_BF16X2(afr[kk][3], e18, e19);
            }
            // ---- PV: D += P x V^T via HMMA ----
            const uint32_t baseB = smb + SM_V + s*VBUF
                                 + (lane & 7)*VSTRIDE + ((lane >> 3) & 1)*16;
            #pragma unroll
            for (int nb = 0; nb < 8; nb++) {
                const uint32_t anb = baseB + nb*(8*VSTRIDE);
                #pragma unroll
                for (int kk = 0; kk < 4; kk++) {
                    uint32_t b0, b1;
                    ldsm_x2(b0, b1, anb + kk*32);
                    mma16816(acc[nb], afr[kk], b0, b1);
                }
            }
            __syncthreads();
        }

        lden0 += __shfl_xor_sync(0xffffffffu, lden0, 1);
        lden0 += __shfl_xor_sync(0xffffffffu, lden0, 2);
        lden1 += __shfl_xor_sync(0xffffffffu, lden1, 1);
        lden1 += __shfl_xor_sync(0xffffffffu, lden1, 2);
        if (q == 0) {
            g_pl[(jq*BB + b)*HWN + i0 + wid*16 + rr]     = lden0;
            g_pl[(jq*BB + b)*HWN + i0 + wid*16 + rr + 8] = lden1;
        }

        float* Db = (float*)sm;
        {
            const int iL = wid*16 + rr;
            #pragma unroll
            for (int nb = 0; nb < 8; nb++) {
                const int c0 = nb*8 + 2*q;
                Db[ c0   *DSTRIDE + iL    ] = acc[nb][0];
                Db[(c0+1)*DSTRIDE + iL    ] = acc[nb][1];
                Db[ c0   *DSTRIDE + iL + 8] = acc[nb][2];
                Db[(c0+1)*DSTRIDE + iL + 8] = acc[nb][3];
            }
        }
        __syncthreads();
        float* pn = g_pn + (size_t)((jq*BB + b)*CCH)*HWN;
        for (int e = tid; e < 2048; e += 256) {
            int c = e >> 5, xx = (e & 31) * 4;
            *(float4*)&pn[(size_t)c*HWN + i0 + xx] = *(float4*)&Db[c*DSTRIDE + xx];
        }
    } else {
        // ---------------- gram partial + last-CTA softmax ----------------
        const int g = bid - 512;          // 0..63
        const int chunk = g >> 1;
        const int b = g & 1;
        const int n0 = chunk * 128;
        float (*t2)[68] = (float(*)[68])sm;
        const float* f = g_cx + (size_t)b*CCH*HWN;
        {
            int r = tid >> 2, nb = tid & 3;
            #pragma unroll
            for (int u = 0; u < 8; u++) {
                int n = nb*32 + u*4;
                float4 v = *(const float4*)&f[(size_t)r*HWN + n0 + n];
                t2[n  ][r] = v.x;
                t2[n+1][r] = v.y;
                t2[n+2][r] = v.z;
                t2[n+3][r] = v.w;
            }
        }
        __syncthreads();
        const int i4 = (tid & 15) * 4, j4 = (tid >> 4) * 4;
        float2 acc[4][2];
        #pragma unroll
        for (int a = 0; a < 4; a++) { acc[a][0] = {0,0}; acc[a][1] = {0,0}; }
        for (int n = 0; n < 128; n++) {
            float4 fi = *(float4*)&t2[n][i4];
            float4 fj = *(float4*)&t2[n][j4];
            float2 j01 = {fj.x, fj.y}, j23 = {fj.z, fj.w};
            float fa[4] = {fi.x, fi.y, fi.z, fi.w};
            #pragma unroll
            for (int a = 0; a < 4; a++) {
                float2 fb = {fa[a], fa[a]};
                acc[a][0] = ffma2(fb, j01, acc[a][0]);
                acc[a][1] = ffma2(fb, j23, acc[a][1]);
            }
        }
        float* gp = g_gramp + (size_t)(chunk*BB + b)*4096;
        #pragma unroll
        for (int a = 0; a < 4; a++) {
            float4 r = {acc[a][0].x, acc[a][0].y, acc[a][1].x, acc[a][1].y};
            *(float4*)&gp[(i4 + a)*64 + j4] = r;
        }
        // completion counter (threadFenceReduction pattern)
        __shared__ unsigned last_flag;
        __syncthreads();
        if (tid == 0) {
            __threadfence();
            unsigned old = atomicAdd(&g_cnt[b], 1u);
            last_flag = (old == 31u);
        }
        __syncthreads();
        if (last_flag) {
            __threadfence();
            float (*red)[65] = (float(*)[65])sm;
            __syncthreads();
            for (int e = tid; e < 4096; e += 256) {
                float s = 0.f;
                #pragma unroll
                for (int ch = 0; ch < 32; ch++)
                    s += g_gramp[(size_t)(ch*BB + b)*4096 + e];
                red[e >> 6][e & 63] = s;
            }
            __syncthreads();
            if (tid < 64) {
                float mn = red[tid][0];
                #pragma unroll 8
                for (int j = 1; j < 64; j++) mn = fminf(mn, red[tid][j]);
                float sum = 0.f;
                #pragma unroll 8
                for (int j = 0; j < 64; j++) {
                    float e = __expf(mn - red[tid][j]);
                    red[tid][j] = e;
                    sum += e;
                }
                float inv = 1.f / sum;
                #pragma unroll 8
                for (int j = 0; j < 64; j++)
                    g_Ac[(b*CCH + tid)*CCH + j] = red[tid][j] * inv;
            }
            if (tid == 0) g_cnt[b] = 0u;   // reset for next graph replay
        }
    }
}

// ============================================================
// EPILOGUE: sum = sg*(Σ pn)/(Σ pl) + sx + cg*(Ac@fmap) + cx   (in smem)
// then out = oW @ sum + ob  → writes d_out directly.
// grid (128 n-tiles of 32, BB), block 512 (thread owns 4 channels).
// ============================================================
__global__ __launch_bounds__(512) void ca_fuse_o_k(
    const float* __restrict__ s_gamma, const float* __restrict__ c_gamma,
    const float* __restrict__ oW, const float* __restrict__ ob,
    float* __restrict__ dout)
{
    __shared__ __align__(16) float ft[64][36];
    __shared__ __align__(16) float As[64][68];   // Ac^T, later reused for oW
    __shared__ float linv[32];
    const int b = blockIdx.y, n0 = blockIdx.x * 32, tid = threadIdx.x;
    const float* f = g_cx + (size_t)b*CCH*HWN;
    for (int e = tid; e < 512; e += 512) {
        int r = e >> 3, c4 = e & 7;
        *(float4*)&ft[r][c4*4] = *(const float4*)&f[(size_t)r*HWN + n0 + c4*4];
    }
    for (int e = tid; e < 1024; e += 512) {
        int c = e >> 4, j4 = (e & 15) * 4;
        float4 a4 = *(const float4*)&g_Ac[(b*CCH + c)*CCH + j4];
        As[j4  ][c] = a4.x;
        As[j4+1][c] = a4.y;
        As[j4+2][c] = a4.z;
        As[j4+3][c] = a4.w;
    }
    if (tid < 32) {
        float l = 0.f;
        #pragma unroll
        for (int qq = 0; qq < NJQ; qq++)
            l += g_pl[(qq*BB + b)*HWN + n0 + tid];
        linv[tid] = s_gamma[0] / l;
    }
    __syncthreads();
    const int n = tid & 31, c0 = (tid >> 5) * 4;   // 16 groups x 4 channels
    float2 acc2[2];
    acc2[0] = make_float2(0.f, 0.f);
    acc2[1] = make_float2(0.f, 0.f);
    for (int jj = 0; jj < 64; jj++) {
        float fv = ft[jj][n];
        float2 fb = {fv, fv};
        acc2[0] = ffma2(fb, *(float2*)&As[jj][c0],     acc2[0]);
        acc2[1] = ffma2(fb, *(float2*)&As[jj][c0 + 2], acc2[1]);
    }
    const float cg = c_gamma[0];
    const float li = linv[n];
    float sums[4];
    #pragma unroll
    for (int p = 0; p < 2; p++) {
        #pragma unroll
        for (int h = 0; h < 2; h++) {
            int c = c0 + p*2 + h;
            size_t idx = (size_t)(b*CCH + c)*HWN + n0 + n;
            float pnsum = 0.f;
            #pragma unroll
            for (int qq = 0; qq < NJQ; qq++)
                pnsum += g_pn[(size_t)((qq*BB + b)*CCH + c)*HWN + n0 + n];
            float ca = h ? acc2[p].y : acc2[p].x;
            sums[p*2 + h] = li*pnsum + g_sx[idx] + cg*ca + ft[c][n];
        }
    }
    __syncthreads();
    #pragma unroll
    for (int u = 0; u < 4; u++) ft[c0 + u][n] = sums[u];
    for (int e = tid; e < 4096; e += 512) {
        int ci = e >> 6, co = e & 63;
        As[ci][co] = oW[co*64 + ci];
    }
    __syncthreads();
    float2 oacc[2];
    oacc[0] = make_float2(0.f, 0.f);
    oacc[1] = make_float2(0.f, 0.f);
    for (int ci = 0; ci < 64; ci++) {
        float sv = ft[ci][n];
        float2 sb2 = {sv, sv};
        oacc[0] = ffma2(sb2, *(float2*)&As[ci][c0],     oacc[0]);
        oacc[1] = ffma2(sb2, *(float2*)&As[ci][c0 + 2], oacc[1]);
    }
    #pragma unroll
    for (int p = 0; p < 2; p++) {
        #pragma unroll
        for (int h = 0; h < 2; h++) {
            int co = c0 + p*2 + h;
            float v = (h ? oacc[p].y : oacc[p].x) + ob[co];
            dout[(size_t)(b*CCH + co)*HWN + n0 + n] = v;
        }
    }
}

// ============================================================
extern "C" void kernel_launch(void* const* d_in, const int* in_sizes, int n_in,
                              void* d_out, int out_size)
{
    const float* x   = (const float*)d_in[0];
    const float* sW  = (const float*)d_in[1];
    const float* sb  = (const float*)d_in[2];
    const float* s_g = (const float*)d_in[3];
    const float* s_b = (const float*)d_in[4];
    const float* s_m = (const float*)d_in[5];
    const float* s_v = (const float*)d_in[6];
    const float* cW  = (const float*)d_in[7];
    const float* cb  = (const float*)d_in[8];
    const float* c_g = (const float*)d_in[9];
    const float* c_b = (const float*)d_in[10];
    const float* c_m = (const float*)d_in[11];
    const float* c_v = (const float*)d_in[12];
    const float* qW  = (const float*)d_in[13];
    const float* qb  = (const float*)d_in[14];
    const float* kW  = (const float*)d_in[15];
    const float* kb  = (const float*)d_in[16];
    const float* vW  = (const float*)d_in[17];
    const float* vb  = (const float*)d_in[18];
    const float* oW  = (const float*)d_in[19];
    const float* ob  = (const float*)d_in[20];
    const float* s_gamma = (const float*)d_in[21];
    const float* c_gamma = (const float*)d_in[22];
    float* out = (float*)d_out;

    conv3_bn_relu<<<dim3(8,16,2*BB), 256>>>(x, sW, sb, s_g, s_b, s_m, s_v,
                                            cW, cb, c_g, c_b, c_m, c_v);
    qkv_k<<<dim3(32,5,BB), 256>>>(x, qW, qb, kW, kb, vW, vb);

    mid_k<<<576, 256>>>();

    ca_fuse_o_k<<<dim3(128,BB), 512>>>(s_gamma, c_gamma, oW, ob, out);
}